// round 8
// baseline (speedup 1.0000x reference)
#include <cuda_runtime.h>
#include <math.h>
#include <stdint.h>

#define NMAX 100000
#define EMAX 1600000
#define HDIM 128
#define C_OUT 20
#define STRIDE 36           // floats per smem chunk row (conflict-free frags)
#define CHUNKB (128 * STRIDE * 4)   // 18432 B per matrix per K-chunk

// ---- static device scratch (no allocation allowed) ----
__device__ float4 g_agg[(size_t)NMAX * HDIM / 4];
__device__ float4 g_h[(size_t)NMAX * HDIM / 4];
__device__ int    g_hist[NMAX];
__device__ int    g_rowptr[NMAX + 1];
__device__ int    g_wofs[NMAX];
__device__ int    g_srcs[EMAX];
__device__ int    g_bsum[128];
__device__ int    g_is64;

// ================= helpers =================

__device__ __forceinline__ uint32_t smem_u32(const void* p) {
    uint32_t a;
    asm("{ .reg .u64 t; cvta.to.shared.u64 t, %1; cvt.u32.u64 %0, t; }" : "=r"(a) : "l"(p));
    return a;
}
__device__ __forceinline__ void cp16(uint32_t dst, const float* src, int pbytes) {
    asm volatile("cp.async.cg.shared.global [%0], [%1], 16, %2;"
                 :: "r"(dst), "l"(src), "r"(pbytes) : "memory");
}
__device__ __forceinline__ void cp_commit() {
    asm volatile("cp.async.commit_group;" ::: "memory");
}
template <int N>
__device__ __forceinline__ void cp_wait() {
    asm volatile("cp.async.wait_group %0;" :: "n"(N) : "memory");
}
// D(16x8) += A(16x8 tf32 row) * B(8x8 tf32 col); raw fp32 bits (HW truncates to tf32)
__device__ __forceinline__ void mma_tf32(float* c, const uint32_t* a, const uint32_t* b) {
    asm volatile(
        "mma.sync.aligned.m16n8k8.row.col.f32.tf32.tf32.f32 "
        "{%0,%1,%2,%3}, {%4,%5,%6,%7}, {%8,%9}, {%0,%1,%2,%3};"
        : "+f"(c[0]), "+f"(c[1]), "+f"(c[2]), "+f"(c[3])
        : "r"(a[0]), "r"(a[1]), "r"(a[2]), "r"(a[3]), "r"(b[0]), "r"(b[1]));
}

// ================= dtype detection for edge_index =================
__global__ void k_detect(const unsigned* __restrict__ ei_raw, int e) {
    int t = threadIdx.x;
    if (t == 0) g_is64 = 1;
    __syncthreads();
    long long stride = (long long)e / 256;
    if (stride < 1) stride = 1;
    long long idx = (long long)t * stride;
    if (idx < (long long)e) {
        unsigned hi = ei_raw[2 * idx + 1];
        if (hi != 0) atomicAnd(&g_is64, 0);
    }
}
__device__ __forceinline__ int load_edge(const void* ei, long long ofs) {
    if (g_is64) return (int)((const long long*)ei)[ofs];
    return ((const int*)ei)[ofs];
}

// ================= CSR build =================

__global__ void k_zero_hist(int n) {
    int i = blockIdx.x * blockDim.x + threadIdx.x;
    if (i < n) g_hist[i] = 0;
}
__global__ void k_hist(const void* __restrict__ ei, int e, int n) {
    int i = blockIdx.x * blockDim.x + threadIdx.x;
    if (i < e) {
        int d = load_edge(ei, (long long)e + i);
        if ((unsigned)d < (unsigned)n) atomicAdd(&g_hist[d], 1);
    }
}
__global__ void k_scan1(int n) {
    __shared__ int sh[512];
    int b = blockIdx.x, t = threadIdx.x;
    int base = b * 2048 + t * 4;
    int s = 0;
#pragma unroll
    for (int i = 0; i < 4; i++) {
        int idx = base + i;
        if (idx < n) s += g_hist[idx];
    }
    sh[t] = s;
    __syncthreads();
    for (int off = 256; off > 0; off >>= 1) {
        if (t < off) sh[t] += sh[t + off];
        __syncthreads();
    }
    if (t == 0) g_bsum[b] = sh[0];
}
__global__ void k_scan2(int nb, int n) {
    __shared__ int sh[128];
    int t = threadIdx.x;
    int v = (t < nb) ? g_bsum[t] : 0;
    sh[t] = v;
    __syncthreads();
    for (int off = 1; off < 128; off <<= 1) {
        int a = (t >= off) ? sh[t - off] : 0;
        __syncthreads();
        sh[t] += a;
        __syncthreads();
    }
    int ex = (t == 0) ? 0 : sh[t - 1];
    if (t < nb) g_bsum[t] = ex;
    if (t == 127) g_rowptr[n] = sh[127];
}
__global__ void k_scan3(int n) {
    __shared__ int sh[512];
    int b = blockIdx.x, t = threadIdx.x;
    int base = b * 2048 + t * 4;
    int v[4];
    int s = 0;
#pragma unroll
    for (int i = 0; i < 4; i++) {
        int idx = base + i;
        v[i] = (idx < n) ? g_hist[idx] : 0;
        s += v[i];
    }
    sh[t] = s;
    __syncthreads();
    for (int off = 1; off < 512; off <<= 1) {
        int a = (t >= off) ? sh[t - off] : 0;
        __syncthreads();
        sh[t] += a;
        __syncthreads();
    }
    int run = g_bsum[b] + ((t == 0) ? 0 : sh[t - 1]);
#pragma unroll
    for (int i = 0; i < 4; i++) {
        int idx = base + i;
        if (idx < n) {
            g_rowptr[idx] = run;
            g_wofs[idx] = run;
            run += v[i];
        }
    }
}
__global__ void k_scatter(const void* __restrict__ ei, int e, int n) {
    int i = blockIdx.x * blockDim.x + threadIdx.x;
    if (i < e) {
        int d = load_edge(ei, (long long)e + i);
        int s = load_edge(ei, i);
        if ((unsigned)d < (unsigned)n && (unsigned)s < (unsigned)n) {
            int pos = atomicAdd(&g_wofs[d], 1);
            if ((unsigned)pos < (unsigned)EMAX) g_srcs[pos] = s;
        }
    }
}

// ================= mean aggregation: warp per node, MLP=4 =================

template <bool SRC_X>
__global__ void k_aggregate(const float4* __restrict__ xin, int n) {
    const float4* X = SRC_X ? xin : (const float4*)g_h;
    int w = (blockIdx.x * blockDim.x + threadIdx.x) >> 5;
    int lane = threadIdx.x & 31;
    if (w >= n) return;
    int beg = g_rowptr[w], end = g_rowptr[w + 1];
    float4 acc = make_float4(0.f, 0.f, 0.f, 0.f);
    int e = beg;
    for (; e + 3 < end; e += 4) {
        int s0 = g_srcs[e], s1 = g_srcs[e + 1], s2 = g_srcs[e + 2], s3 = g_srcs[e + 3];
        float4 v0 = X[(size_t)s0 * 32 + lane];
        float4 v1 = X[(size_t)s1 * 32 + lane];
        float4 v2 = X[(size_t)s2 * 32 + lane];
        float4 v3 = X[(size_t)s3 * 32 + lane];
        acc.x += (v0.x + v1.x) + (v2.x + v3.x);
        acc.y += (v0.y + v1.y) + (v2.y + v3.y);
        acc.z += (v0.z + v1.z) + (v2.z + v3.z);
        acc.w += (v0.w + v1.w) + (v2.w + v3.w);
    }
    for (; e < end; e++) {
        int s0 = g_srcs[e];
        float4 v0 = X[(size_t)s0 * 32 + lane];
        acc.x += v0.x; acc.y += v0.y; acc.z += v0.z; acc.w += v0.w;
    }
    int cnt = end - beg;
    float inv = 1.0f / (float)(cnt > 0 ? cnt : 1);
    float4 r = make_float4(acc.x * inv, acc.y * inv, acc.z * inv, acc.w * inv);
    g_agg[(size_t)w * 32 + lane] = r;
}

// ================= cp.async-pipelined tf32 GEMM =================
// C[128x128 tile] = relu( Am @ Wl^T [+ Ax @ Wr^T] + bias ); MODE 2 additionally
// fuses the head: out = sigmoid( C @ Wm2^T + bm2 ).
// 256 threads = 8 warps (4M x 2N), warp tile 32x64, m16n8k8, K chunks of 32,
// 2-stage cp.async pipeline, raw fp32 fed to tf32 MMA (HW truncation).
// MODE 0: Am=g_agg, Ax=xparam -> g_h ; MODE 1: Am=g_agg, Ax=g_h -> g_h
// MODE 2: Am=g_h, single       -> out (head fused)

template <int MODE>
__global__ __launch_bounds__(256, 1) void k_gemm(
    const float* __restrict__ xparam,
    const float* __restrict__ Wl, const float* __restrict__ Wr,
    const float* __restrict__ bias,
    const float* __restrict__ Wm2, const float* __restrict__ bm2,
    float* __restrict__ outp, int n)
{
    constexpr bool DUAL = (MODE != 2);
    constexpr int NMAT = DUAL ? 4 : 2;
    constexpr int STAGEB = NMAT * CHUNKB;

    extern __shared__ float dsm[];
    uint32_t sbase = smem_u32(dsm);
    __shared__ float sbias[128];

    const float* Am = (MODE == 2) ? (const float*)g_h : (const float*)g_agg;
    const float* Ax = (MODE == 0) ? xparam : (const float*)g_h;
    float* Ch = (float*)g_h;

    int tid = threadIdx.x;
    int lane = tid & 31, wid = tid >> 5;
    int wm = wid >> 1, wn = wid & 1;
    int g = lane >> 2, t = lane & 3;
    int row0 = blockIdx.x * 128;

    if (tid < 128) sbias[tid] = bias[tid];

    float c[2][8][4];
#pragma unroll
    for (int mi = 0; mi < 2; mi++)
#pragma unroll
        for (int ni = 0; ni < 8; ni++)
#pragma unroll
            for (int q = 0; q < 4; q++) c[mi][ni][q] = 0.f;

    // ---- async chunk loader: K-chunk ck (32 cols) into stage buffer b ----
    auto load_chunk = [&](int ck, int b) {
        int kc = ck * 32;
        uint32_t stage = sbase + b * STAGEB;
#pragma unroll
        for (int rlot = 0; rlot < 4; rlot++) {
            int i = tid + rlot * 256;          // 1024 slots: row(128) x q(8)
            int row = i >> 3, q = i & 7;
            uint32_t doff = row * (STRIDE * 4) + q * 16;
            int grow = row0 + row;
            const float* sa = Am + ((size_t)(grow < n ? grow : 0) * 128 + kc + q * 4);
            cp16(stage + doff, sa, grow < n ? 16 : 0);
            cp16(stage + CHUNKB + doff, Wl + ((size_t)row * 128 + kc + q * 4), 16);
            if (DUAL) {
                const float* sx = Ax + ((size_t)(grow < n ? grow : 0) * 128 + kc + q * 4);
                cp16(stage + 2 * CHUNKB + doff, sx, grow < n ? 16 : 0);
                cp16(stage + 3 * CHUNKB + doff, Wr + ((size_t)row * 128 + kc + q * 4), 16);
            }
        }
    };

    // ---- compute one chunk from stage buffer b ----
    auto compute_chunk = [&](int b) {
        const uint32_t* st = (const uint32_t*)dsm + (size_t)b * (STAGEB / 4);
        const uint32_t* sAm = st;
        const uint32_t* sWl = st + CHUNKB / 4;
        const uint32_t* sAx = st + 2 * (CHUNKB / 4);
        const uint32_t* sWr = st + 3 * (CHUNKB / 4);
#pragma unroll
        for (int k0 = 0; k0 < 32; k0 += 8) {
            uint32_t aM[2][4], aX[2][4];
#pragma unroll
            for (int mi = 0; mi < 2; mi++) {
                int rb = wm * 32 + mi * 16;
                const uint32_t* p0 = sAm + (rb + g) * STRIDE + k0 + t;
                const uint32_t* p1 = sAm + (rb + 8 + g) * STRIDE + k0 + t;
                aM[mi][0] = p0[0]; aM[mi][1] = p1[0]; aM[mi][2] = p0[4]; aM[mi][3] = p1[4];
                if (DUAL) {
                    const uint32_t* q0 = sAx + (rb + g) * STRIDE + k0 + t;
                    const uint32_t* q1 = sAx + (rb + 8 + g) * STRIDE + k0 + t;
                    aX[mi][0] = q0[0]; aX[mi][1] = q1[0]; aX[mi][2] = q0[4]; aX[mi][3] = q1[4];
                }
            }
#pragma unroll
            for (int ni = 0; ni < 8; ni++) {
                const uint32_t* p = sWl + (wn * 64 + ni * 8 + g) * STRIDE + k0 + t;
                uint32_t bL[2] = { p[0], p[4] };
#pragma unroll
                for (int mi = 0; mi < 2; mi++) mma_tf32(c[mi][ni], aM[mi], bL);
                if (DUAL) {
                    const uint32_t* q = sWr + (wn * 64 + ni * 8 + g) * STRIDE + k0 + t;
                    uint32_t bR[2] = { q[0], q[4] };
#pragma unroll
                    for (int mi = 0; mi < 2; mi++) mma_tf32(c[mi][ni], aX[mi], bR);
                }
            }
        }
    };

    // ---- 2-stage pipeline over 4 K-chunks ----
    load_chunk(0, 0);
    cp_commit();
#pragma unroll
    for (int ck = 0; ck < 4; ck++) {
        if (ck < 3) { load_chunk(ck + 1, (ck + 1) & 1); cp_commit(); }
        if (ck < 3) cp_wait<1>(); else cp_wait<0>();
        __syncthreads();
        compute_chunk(ck & 1);
        __syncthreads();
    }

    if (MODE != 2) {
        // ---- epilogue: bias + relu -> g_h ----
#pragma unroll
        for (int mi = 0; mi < 2; mi++) {
#pragma unroll
            for (int h = 0; h < 2; h++) {
                int row = row0 + wm * 32 + mi * 16 + h * 8 + g;
                if (row >= n) continue;
                float* dst = Ch + (size_t)row * 128;
#pragma unroll
                for (int ni = 0; ni < 8; ni++) {
                    int col = wn * 64 + ni * 8 + 2 * t;
                    float2 o;
                    o.x = fmaxf(c[mi][ni][h * 2 + 0] + sbias[col], 0.f);
                    o.y = fmaxf(c[mi][ni][h * 2 + 1] + sbias[col + 1], 0.f);
                    *(float2*)(dst + col) = o;
                }
            }
        }
    } else {
        // ---- fused head: t1=relu(C+bias) in smem; out=sigmoid(t1@Wm2^T+bm2) ----
        float* sOut = dsm;                     // 128 x 132
        float* sW2 = dsm + 128 * 132;          // 20 x 128
        float* sb2 = sW2 + C_OUT * 128;        // 20
#pragma unroll
        for (int mi = 0; mi < 2; mi++)
#pragma unroll
            for (int h = 0; h < 2; h++) {
                int rl = wm * 32 + mi * 16 + h * 8 + g;
#pragma unroll
                for (int ni = 0; ni < 8; ni++) {
                    int col = wn * 64 + ni * 8 + 2 * t;
                    sOut[rl * 132 + col]     = fmaxf(c[mi][ni][h * 2 + 0] + sbias[col], 0.f);
                    sOut[rl * 132 + col + 1] = fmaxf(c[mi][ni][h * 2 + 1] + sbias[col + 1], 0.f);
                }
            }
        for (int i = tid; i < C_OUT * 128; i += 256) sW2[i] = Wm2[i];
        if (tid < C_OUT) sb2[tid] = bm2[tid];
        __syncthreads();

        for (int r = 0; r < 16; r++) {
            int rl = wid * 16 + r;
            int grow = row0 + rl;
            if (grow >= n) continue;
            float4 hv = *((const float4*)(sOut + rl * 132) + lane);
#pragma unroll
            for (int o = 0; o < C_OUT; o++) {
                float4 wv = *((const float4*)(sW2 + o * 128) + lane);
                float p = hv.x * wv.x + hv.y * wv.y + hv.z * wv.z + hv.w * wv.w;
                p += __shfl_xor_sync(0xFFFFFFFFu, p, 16);
                p += __shfl_xor_sync(0xFFFFFFFFu, p, 8);
                p += __shfl_xor_sync(0xFFFFFFFFu, p, 4);
                p += __shfl_xor_sync(0xFFFFFFFFu, p, 2);
                p += __shfl_xor_sync(0xFFFFFFFFu, p, 1);
                if (lane == o) {
                    float z = p + sb2[o];
                    outp[(size_t)grow * C_OUT + o] = 1.f / (1.f + __expf(-z));
                }
            }
        }
    }
}

// ================= launch =================

extern "C" void kernel_launch(void* const* d_in, const int* in_sizes, int n_in,
                              void* d_out, int out_size)
{
    const float* x   = (const float*)d_in[0];
    const void*  ei  = d_in[1];
    const float* W1l = (const float*)d_in[2];
    const float* b1  = (const float*)d_in[3];
    const float* W1r = (const float*)d_in[4];
    const float* W2l = (const float*)d_in[5];
    const float* b2  = (const float*)d_in[6];
    const float* W2r = (const float*)d_in[7];
    const float* Wm1 = (const float*)d_in[8];
    const float* bm1 = (const float*)d_in[9];
    const float* Wm2 = (const float*)d_in[10];
    const float* bm2 = (const float*)d_in[11];
    float* out = (float*)d_out;

    int n = in_sizes[0] / HDIM;
    int e = in_sizes[1] / 2;
    int ntiles = (n + 127) / 128;

    const int SMEM_DUAL = 2 * 4 * CHUNKB;                        // 147456
    int smem_m2_pipe = 2 * 2 * CHUNKB;                           // 73728
    int smem_m2_epi  = (128 * 132 + C_OUT * 128 + C_OUT) * 4;    // 77904
    const int SMEM_M2 = smem_m2_pipe > smem_m2_epi ? smem_m2_pipe : smem_m2_epi;

    cudaFuncSetAttribute(k_gemm<0>, cudaFuncAttributeMaxDynamicSharedMemorySize, SMEM_DUAL);
    cudaFuncSetAttribute(k_gemm<1>, cudaFuncAttributeMaxDynamicSharedMemorySize, SMEM_DUAL);
    cudaFuncSetAttribute(k_gemm<2>, cudaFuncAttributeMaxDynamicSharedMemorySize, SMEM_M2);

    // dtype detection + CSR build
    k_detect<<<1, 256>>>((const unsigned*)ei, e);
    k_zero_hist<<<(n + 255) / 256, 256>>>(n);
    k_hist<<<(e + 255) / 256, 256>>>(ei, e, n);
    int nb = (n + 2047) / 2048;
    k_scan1<<<nb, 512>>>(n);
    k_scan2<<<1, 128>>>(nb, n);
    k_scan3<<<nb, 512>>>(n);
    k_scatter<<<(e + 255) / 256, 256>>>(ei, e, n);

    int aggBlocks = (n + 7) / 8;

    // layer 1
    k_aggregate<true><<<aggBlocks, 256>>>((const float4*)x, n);
    k_gemm<0><<<ntiles, 256, SMEM_DUAL>>>(x, W1l, W1r, b1, nullptr, nullptr, nullptr, n);
    // layer 2
    k_aggregate<false><<<aggBlocks, 256>>>(nullptr, n);
    k_gemm<1><<<ntiles, 256, SMEM_DUAL>>>(nullptr, W2l, W2r, b2, nullptr, nullptr, nullptr, n);
    // MLP + fused head
    k_gemm<2><<<ntiles, 256, SMEM_M2>>>(nullptr, Wm1, nullptr, bm1, Wm2, bm2, out, n);
}